// round 14
// baseline (speedup 1.0000x reference)
#include <cuda_runtime.h>
#include <cuda_fp16.h>
#include <cstdint>

#define NB 4
#define ND 128
#define NK 256
#define NS 256
#define NJ 257
#define NO 256
#define TOUT 32768

// ---------------- scratch (A and W stored PRE-SWIZZLED for bulk copy) ----------------
__device__ __align__(128) __half g_Af[(size_t)NB*NJ*128*ND];  // [b][j] tiles, 32KB each, swizzled
__device__ __align__(128) __half g_W1f[NO*ND];                // 64KB swizzled image
__device__ __align__(128) __half g_W2f[NO*ND];                // 64KB swizzled image

// smem map (bytes)
#define SM_B1 0
#define SM_B2 1024
#define SM_W1 2048
#define SM_W2 (SM_W1 + 65536)
#define SM_A  (SM_W2 + 65536)
#define SM_Z  (SM_A + 32768)
#define SM_MB (SM_Z + 65536)           // 2 mbarriers (16 B)
#define SM_TOT (SM_MB + 128)           // 231552

__device__ __forceinline__ uint32_t smem_u32(const void* p) {
    uint32_t a;
    asm("{ .reg .u64 t; cvta.to.shared.u64 t, %1; cvt.u32.u64 %0, t; }" : "=r"(a) : "l"(p));
    return a;
}
// standard swizzle (W/A regions) — also used host-side-of-gmem by prep
__device__ __forceinline__ uint32_t swz(uint32_t row, uint32_t byteCol) {
    return row * 256u + ((((byteCol >> 4) ^ (row & 7)) << 4) | (byteCol & 15));
}
// Z-region swizzle (permuted rows)
__device__ __forceinline__ uint32_t swzZ(uint32_t row, uint32_t byteCol) {
    uint32_t f = (row ^ (row >> 3)) & 7u;
    return row * 256u + ((((byteCol >> 4) ^ f) << 4) | (byteCol & 15));
}
#define LDSM4(r0,r1,r2,r3,addr) \
    asm volatile("ldmatrix.sync.aligned.m8n8.x4.shared.b16 {%0,%1,%2,%3}, [%4];" \
        : "=r"(r0),"=r"(r1),"=r"(r2),"=r"(r3) : "r"(addr))

#define MBAR_INIT(a, c) \
    asm volatile("mbarrier.init.shared.b64 [%0], %1;" :: "r"(a), "r"((uint32_t)(c)) : "memory")
#define MBAR_EXPECT_TX(a, bytes) \
    asm volatile("mbarrier.arrive.expect_tx.shared.b64 _, [%0], %1;" :: "r"(a), "r"((uint32_t)(bytes)) : "memory")
#define BULK_G2S(dst, src, bytes, mbar) \
    asm volatile("cp.async.bulk.shared::cluster.global.mbarrier::complete_tx::bytes [%0], [%1], %2, [%3];" \
        :: "r"(dst), "l"(src), "r"((uint32_t)(bytes)), "r"(mbar) : "memory")

__device__ __forceinline__ void mbar_wait(uint32_t mbar, uint32_t parity) {
    uint32_t done;
    asm volatile("{\n\t.reg .pred p;\n\tmbarrier.try_wait.parity.acquire.cta.shared::cta.b64 p, [%1], %2;\n\tselp.b32 %0, 1, 0, p;\n\t}"
        : "=r"(done) : "r"(mbar), "r"(parity) : "memory");
    if (!done) {
        asm volatile("{\n\t.reg .pred P1;\n\tWL_%=:\n\tmbarrier.try_wait.parity.acquire.cta.shared::cta.b64 P1, [%0], %1, 0x989680;\n\t@P1 bra.uni WD_%=;\n\tbra.uni WL_%=;\n\tWD_%=:\n\t}"
            :: "r"(mbar), "r"(parity) : "memory");
    }
}

__device__ __forceinline__ void mma16816(float d[4], const uint32_t a[4], uint32_t b0, uint32_t b1) {
    asm volatile("mma.sync.aligned.m16n8k16.row.col.f32.f16.f16.f32 "
        "{%0,%1,%2,%3}, {%4,%5,%6,%7}, {%8,%9}, {%0,%1,%2,%3};"
        : "+f"(d[0]), "+f"(d[1]), "+f"(d[2]), "+f"(d[3])
        : "r"(a[0]), "r"(a[1]), "r"(a[2]), "r"(a[3]), "r"(b0), "r"(b1));
}

// 32x64 warp-tile GEMM over K=128 with explicit fragment double-buffering (proven R13).
template<bool BZ>
__device__ __forceinline__ void gemm_pipe(uint32_t uAop, uint32_t uBop,
                                          int ar, int br, uint32_t acb, uint32_t bcb,
                                          float acc[2][8][4])
{
    uint32_t af[2][2][4], bf[2][4][4];
#pragma unroll
    for (int mt = 0; mt < 2; mt++)
        LDSM4(af[0][mt][0], af[0][mt][1], af[0][mt][2], af[0][mt][3],
              uAop + swz(ar + mt * 16, acb));
#pragma unroll
    for (int ng = 0; ng < 4; ng++) {
        uint32_t off = BZ ? swzZ(br + ng * 16, bcb) : swz(br + ng * 16, bcb);
        LDSM4(bf[0][ng][0], bf[0][ng][1], bf[0][ng][2], bf[0][ng][3], uBop + off);
    }
#pragma unroll
    for (int ks = 0; ks < 8; ks++) {
        int cur = ks & 1, nxt = cur ^ 1;
        if (ks < 7) {
            uint32_t kb = (uint32_t)(ks + 1) * 32;
#pragma unroll
            for (int mt = 0; mt < 2; mt++)
                LDSM4(af[nxt][mt][0], af[nxt][mt][1], af[nxt][mt][2], af[nxt][mt][3],
                      uAop + swz(ar + mt * 16, kb + acb));
#pragma unroll
            for (int ng = 0; ng < 4; ng++) {
                uint32_t off = BZ ? swzZ(br + ng * 16, kb + bcb) : swz(br + ng * 16, kb + bcb);
                LDSM4(bf[nxt][ng][0], bf[nxt][ng][1], bf[nxt][ng][2], bf[nxt][ng][3], uBop + off);
            }
        }
#pragma unroll
        for (int mt = 0; mt < 2; mt++)
#pragma unroll
            for (int ng = 0; ng < 4; ng++) {
                mma16816(acc[mt][2 * ng],     af[cur][mt], bf[cur][ng][0], bf[cur][ng][2]);
                mma16816(acc[mt][2 * ng + 1], af[cur][mt], bf[cur][ng][1], bf[cur][ng][3]);
            }
    }
}

// ---------------- prep: W fp16 convert + OLA-presummed A, BOTH written pre-swizzled ----------------
__global__ void prep_all(const float* __restrict__ x, const float* __restrict__ pw_ptr,
                         const float* __restrict__ w1, const float* __restrict__ w2)
{
    int tx = threadIdx.x, ty = threadIdx.y;
    int tid = ty * 32 + tx;
    if (blockIdx.z == NB * 128) {
        // W convert: row = o, byteCol = 2*d, swizzled byte image
        char* w1B = (char*)g_W1f;
        char* w2B = (char*)g_W2f;
        int flat = ((int)blockIdx.x * 2 + (int)blockIdx.y) * 256 + tid;
        for (; flat < 2 * NO * ND; flat += 18 * 256) {
            int m = flat >> 15;             // 0 = W1, 1 = W2
            int i = flat & 32767;
            int o = i >> 7, d = i & 127;
            uint32_t off = swz((uint32_t)o, (uint32_t)(2 * d));
            if (m == 0) *(__half*)(w1B + off) = __float2half_rn(w1[i]);
            else        *(__half*)(w2B + off) = __float2half_rn(w2[i]);
        }
        return;
    }
    __shared__ float t[64][33];
    int b = blockIdx.z >> 7, p = blockIdx.z & 127;
    int j0 = blockIdx.x * 32, d0 = blockIdx.y * 64;
    float pw = *pw_ptr;
#pragma unroll
    for (int i = 0; i < 8; i++) {
        int d = d0 + ty + i * 8;
        int jj = j0 + tx;
        float acc = 0.f;
        if (jj < 256) {
            float v = x[(((size_t)b * ND + d) * NK + p) * NS + jj];
            acc += (v >= 0.f) ? v : pw * v;
        }
        if (jj >= 1 && jj <= 256) {
            float v = x[(((size_t)b * ND + d) * NK + p + 128) * NS + jj - 1];
            acc += (v >= 0.f) ? v : pw * v;
        }
        t[ty + i * 8][tx] = acc;
    }
    __syncthreads();
    char* aB = (char*)g_Af;
#pragma unroll
    for (int i = 0; i < 4; i++) {
        int jl = ty + i * 8;
        int jj = j0 + jl;
        if (jj <= 256) {
            __half2 hv;
            hv.x = __float2half_rn(t[2 * tx][jl]);
            hv.y = __float2half_rn(t[2 * tx + 1][jl]);
            size_t tileBase = (size_t)(b * NJ + jj) * 32768;
            uint32_t off = swz((uint32_t)p, (uint32_t)(2 * d0 + 4 * tx));
            *(__half2*)(aB + tileBase + off) = hv;
        }
    }
}

// ---------------- fused main kernel: bulk-copy prologue, pipelined GEMMs ----------------
__global__ __launch_bounds__(512, 1) void main_kernel(
    const float* __restrict__ b1g, const float* __restrict__ b2g, float* __restrict__ out)
{
    extern __shared__ char smc[];
    uint32_t sb = smem_u32(smc);
    float* s_b1 = (float*)(smc + SM_B1);
    float* s_b2 = (float*)(smc + SM_B2);
    int tid = threadIdx.x, w = tid >> 5, lane = tid & 31;
    int j = blockIdx.x, b = blockIdx.y;
    int pw = (w & 3) * 32, ow = (w >> 2) * 64;
    uint32_t mb0 = sb + SM_MB, mb1 = sb + SM_MB + 8;

    if (tid == 0) { MBAR_INIT(mb0, 1); MBAR_INIT(mb1, 1); }
    __syncthreads();
    if (tid == 0) {
        uint64_t gW1, gW2, gA;
        asm("cvta.to.global.u64 %0, %1;" : "=l"(gW1) : "l"((const void*)g_W1f));
        asm("cvta.to.global.u64 %0, %1;" : "=l"(gW2) : "l"((const void*)g_W2f));
        asm("cvta.to.global.u64 %0, %1;" : "=l"(gA)  : "l"((const void*)g_Af));
        gA += (size_t)(b * NJ + j) * 32768;
        MBAR_EXPECT_TX(mb0, 65536 + 32768);
        BULK_G2S(sb + SM_W1, gW1, 65536, mb0);
        BULK_G2S(sb + SM_A,  gA,  32768, mb0);
        MBAR_EXPECT_TX(mb1, 65536);
        BULK_G2S(sb + SM_W2, gW2, 65536, mb1);
    }
    if (tid < 256) { s_b1[tid] = b1g[tid]; s_b2[tid] = b2g[tid]; }
    mbar_wait(mb0, 0);       // W1 + A landed (W2 in flight, overlaps GEMM1)
    __syncthreads();         // bias visibility

    // operand lane patterns
    int arow = lane & 15;
    uint32_t acb = (uint32_t)(lane >> 4) << 4;
    int brow = ((lane >> 3) & 1) * 8 + (lane & 7);
    uint32_t bcb = (uint32_t)((lane >> 4) & 1) << 4;
    uint32_t uW1 = sb + SM_W1, uW2 = sb + SM_W2, uA = sb + SM_A;
    int lr = lane >> 2, lc = (lane & 3) << 1;

    float acc[2][8][4];

    // ---- GEMM1: D1[p=128][o=256] = A[p][d] * W1[o][d] ----
#pragma unroll
    for (int mt = 0; mt < 2; mt++)
#pragma unroll
        for (int nt = 0; nt < 8; nt++)
#pragma unroll
            for (int q = 0; q < 4; q++) acc[mt][nt][q] = 0.f;
    gemm_pipe<false>(uA, uW1, pw + arow, ow + brow, acb, bcb, acc);

    // ---- epilogue1: Z = relu(D1 + nf*b1) -> fp16 at PERMUTED rows (no sync needed) ----
    float nf = (j == 0 || j == 256) ? 1.f : 2.f;
    int cW = ow >> 7;
    char* zB = smc + SM_Z + cW * 32768;
#pragma unroll
    for (int mt = 0; mt < 2; mt++) {
#pragma unroll
        for (int nt = 0; nt < 8; nt++) {
            int o = ow + nt * 8 + lc;
            int e = o & 127;
            float b0v = nf * s_b1[o], b1v = nf * s_b1[o + 1];
#pragma unroll
            for (int hf = 0; hf < 2; hf++) {
                int p = pw + mt * 16 + lr + hf * 8;
                int pl = p & 63;
                int nl = ((pl >> 4) << 4) + (((pl >> 1) & 1) << 3)
                       + (((pl >> 2) & 3) << 1) + (pl & 1);
                uint32_t row = (uint32_t)((p & 64) + nl);
                __half2 hv;
                hv.x = __float2half_rn(fmaxf(acc[mt][nt][hf * 2]     + b0v, 0.f));
                hv.y = __float2half_rn(fmaxf(acc[mt][nt][hf * 2 + 1] + b1v, 0.f));
                *(uint32_t*)(zB + swzZ(row, (uint32_t)e << 1)) = *(uint32_t*)&hv;
            }
        }
    }
    mbar_wait(mb1, 0);       // W2 landed
    __syncthreads();         // Z visible to all

    // ---- GEMM2 (transposed): D2^T[o2=256][p=128] = W2[o2][e] * Z_c[p][e] ----
    int o2w = (w & 7) * 32, pw2 = (w >> 3) * 64;
    int ar2 = o2w + arow, br2 = pw2 + brow;
#pragma unroll 1
    for (int c = 0; c < 2; c++) {
        uint32_t uZ = sb + SM_Z + c * 32768;
#pragma unroll
        for (int mt = 0; mt < 2; mt++)
#pragma unroll
            for (int nt = 0; nt < 8; nt++)
#pragma unroll
                for (int q = 0; q < 4; q++) acc[mt][nt][q] = 0.f;
        gemm_pipe<true>(uW2, uZ, ar2, br2, acb, bcb, acc);

        // ---- out epilogue: 4x float4 contiguous per row ----
        int l0 = j * 128 - 64;
        int t4 = lane & 3;
        bool valid = (j > 0 || pw2 == 64) && (j < 256 || pw2 == 0);
        if (valid) {
            float* ob = out + (size_t)(b * 2 + c) * NO * TOUT;
#pragma unroll
            for (int mt = 0; mt < 2; mt++) {
#pragma unroll
                for (int hf = 0; hf < 2; hf++) {
                    int o2 = o2w + mt * 16 + lr + hf * 8;
                    float bo = s_b2[o2];
                    float* orow = ob + (size_t)o2 * TOUT + l0 + pw2 + t4 * 4;
#pragma unroll
                    for (int q = 0; q < 4; q++) {
                        float4 v;
                        v.x = acc[mt][2 * q][hf * 2]         + bo;
                        v.y = acc[mt][2 * q][hf * 2 + 1]     + bo;
                        v.z = acc[mt][2 * q + 1][hf * 2]     + bo;
                        v.w = acc[mt][2 * q + 1][hf * 2 + 1] + bo;
                        *(float4*)(orow + 16 * q) = v;
                    }
                }
            }
        }
    }
}

// ---------------------------------------------------------------------------
extern "C" void kernel_launch(void* const* d_in, const int* in_sizes, int n_in,
                              void* d_out, int out_size) {
    const float* x  = (const float*)d_in[0];
    const float* pw = (const float*)d_in[1];
    const float* w1 = (const float*)d_in[2];
    const float* b1 = (const float*)d_in[3];
    const float* w2 = (const float*)d_in[4];
    const float* b2 = (const float*)d_in[5];
    float* out = (float*)d_out;

    cudaFuncSetAttribute(main_kernel, cudaFuncAttributeMaxDynamicSharedMemorySize, SM_TOT);

    prep_all<<<dim3(9, 2, NB * 128 + 1), dim3(32, 8)>>>(x, pw, w1, w2);
    main_kernel<<<dim3(NJ, NB), 512, SM_TOT>>>(b1, b2, out);
}

// round 15
// speedup vs baseline: 1.3924x; 1.3924x over previous
#include <cuda_runtime.h>
#include <cuda_fp16.h>
#include <cstdint>

#define NB 4
#define ND 128
#define NK 256
#define NS 256
#define NJ 257
#define NO 256
#define TOUT 32768
#define NTILE (NB * NJ)      // 1028
#define GRID_MAIN 148

// ---------------- scratch ----------------
__device__ __half g_Af[(size_t)NB*NJ*128*ND];   // presummed OLA frames, fp16 [b][j][p][d]
__device__ __half g_W1f[NO*ND];                 // [o][d]
__device__ __half g_W2f[NO*ND];                 // [o2][e]

// smem map (bytes) — all regions disjoint; 231424 total (1 CTA/SM)
#define SM_B1 0
#define SM_B2 1024
#define SM_W1 2048
#define SM_W2 (SM_W1 + 65536)
#define SM_A  (SM_W2 + 65536)
#define SM_Z  (SM_A + 32768)
#define SM_TOT (SM_Z + 65536)          // 231424

__device__ __forceinline__ uint32_t smem_u32(const void* p) {
    uint32_t a;
    asm("{ .reg .u64 t; cvta.to.shared.u64 t, %1; cvt.u32.u64 %0, t; }" : "=r"(a) : "l"(p));
    return a;
}
// standard swizzle (W/A regions)
__device__ __forceinline__ uint32_t swz(uint32_t row, uint32_t byteCol) {
    return row * 256u + ((((byteCol >> 4) ^ (row & 7)) << 4) | (byteCol & 15));
}
// Z-region swizzle (permuted rows)
__device__ __forceinline__ uint32_t swzZ(uint32_t row, uint32_t byteCol) {
    uint32_t f = (row ^ (row >> 3)) & 7u;
    return row * 256u + ((((byteCol >> 4) ^ f) << 4) | (byteCol & 15));
}
#define LDSM4(r0,r1,r2,r3,addr) \
    asm volatile("ldmatrix.sync.aligned.m8n8.x4.shared.b16 {%0,%1,%2,%3}, [%4];" \
        : "=r"(r0),"=r"(r1),"=r"(r2),"=r"(r3) : "r"(addr))
#define CP16(dst, src) \
    asm volatile("cp.async.cg.shared.global [%0], [%1], 16;" :: "r"(dst), "l"(src) : "memory")
#define CP_COMMIT() asm volatile("cp.async.commit_group;" ::: "memory")
#define CP_WAIT(n)  asm volatile("cp.async.wait_group %0;" :: "n"(n) : "memory")

__device__ __forceinline__ void mma16816(float d[4], const uint32_t a[4], uint32_t b0, uint32_t b1) {
    asm volatile("mma.sync.aligned.m16n8k16.row.col.f32.f16.f16.f32 "
        "{%0,%1,%2,%3}, {%4,%5,%6,%7}, {%8,%9}, {%0,%1,%2,%3};"
        : "+f"(d[0]), "+f"(d[1]), "+f"(d[2]), "+f"(d[3])
        : "r"(a[0]), "r"(a[1]), "r"(a[2]), "r"(a[3]), "r"(b0), "r"(b1));
}

// 32x64 warp-tile GEMM over K=128 with explicit fragment double-buffering (proven R13).
template<bool BZ>
__device__ __forceinline__ void gemm_pipe(uint32_t uAop, uint32_t uBop,
                                          int ar, int br, uint32_t acb, uint32_t bcb,
                                          float acc[2][8][4])
{
    uint32_t af[2][2][4], bf[2][4][4];
#pragma unroll
    for (int mt = 0; mt < 2; mt++)
        LDSM4(af[0][mt][0], af[0][mt][1], af[0][mt][2], af[0][mt][3],
              uAop + swz(ar + mt * 16, acb));
#pragma unroll
    for (int ng = 0; ng < 4; ng++) {
        uint32_t off = BZ ? swzZ(br + ng * 16, bcb) : swz(br + ng * 16, bcb);
        LDSM4(bf[0][ng][0], bf[0][ng][1], bf[0][ng][2], bf[0][ng][3], uBop + off);
    }
#pragma unroll
    for (int ks = 0; ks < 8; ks++) {
        int cur = ks & 1, nxt = cur ^ 1;
        if (ks < 7) {
            uint32_t kb = (uint32_t)(ks + 1) * 32;
#pragma unroll
            for (int mt = 0; mt < 2; mt++)
                LDSM4(af[nxt][mt][0], af[nxt][mt][1], af[nxt][mt][2], af[nxt][mt][3],
                      uAop + swz(ar + mt * 16, kb + acb));
#pragma unroll
            for (int ng = 0; ng < 4; ng++) {
                uint32_t off = BZ ? swzZ(br + ng * 16, kb + bcb) : swz(br + ng * 16, kb + bcb);
                LDSM4(bf[nxt][ng][0], bf[nxt][ng][1], bf[nxt][ng][2], bf[nxt][ng][3], uBop + off);
            }
        }
#pragma unroll
        for (int mt = 0; mt < 2; mt++)
#pragma unroll
            for (int ng = 0; ng < 4; ng++) {
                mma16816(acc[mt][2 * ng],     af[cur][mt], bf[cur][ng][0], bf[cur][ng][2]);
                mma16816(acc[mt][2 * ng + 1], af[cur][mt], bf[cur][ng][1], bf[cur][ng][3]);
            }
    }
}

// ---------------- prep: W fp16 convert + OLA-presummed A (proven, plain layout) ----------------
__global__ void prep_all(const float* __restrict__ x, const float* __restrict__ pw_ptr,
                         const float* __restrict__ w1, const float* __restrict__ w2)
{
    int tx = threadIdx.x, ty = threadIdx.y;
    int tid = ty * 32 + tx;
    if (blockIdx.z == NB * 128) {
        int flat = ((int)blockIdx.x * 2 + (int)blockIdx.y) * 256 + tid;
        for (; flat < 2 * NO * ND; flat += 18 * 256) {
            if (flat < NO * ND) g_W1f[flat] = __float2half_rn(w1[flat]);
            else                g_W2f[flat - NO * ND] = __float2half_rn(w2[flat - NO * ND]);
        }
        return;
    }
    __shared__ float t[64][33];
    int b = blockIdx.z >> 7, p = blockIdx.z & 127;
    int j0 = blockIdx.x * 32, d0 = blockIdx.y * 64;
    float pw = *pw_ptr;
#pragma unroll
    for (int i = 0; i < 8; i++) {
        int d = d0 + ty + i * 8;
        int jj = j0 + tx;
        float acc = 0.f;
        if (jj < 256) {
            float v = x[(((size_t)b * ND + d) * NK + p) * NS + jj];
            acc += (v >= 0.f) ? v : pw * v;
        }
        if (jj >= 1 && jj <= 256) {
            float v = x[(((size_t)b * ND + d) * NK + p + 128) * NS + jj - 1];
            acc += (v >= 0.f) ? v : pw * v;
        }
        t[ty + i * 8][tx] = acc;
    }
    __syncthreads();
#pragma unroll
    for (int i = 0; i < 4; i++) {
        int jl = ty + i * 8;
        int jj = j0 + jl;
        if (jj <= 256) {
            __half2 hv;
            hv.x = __float2half_rn(t[2 * tx][jl]);
            hv.y = __float2half_rn(t[2 * tx + 1][jl]);
            *(__half2*)&g_Af[(((size_t)b * NJ + jj) * 128 + p) * ND + d0 + 2 * tx] = hv;
        }
    }
}

// ---------------- persistent fused main kernel: W resident, A pipelined across tiles ----------------
__global__ __launch_bounds__(512, 1) void main_kernel(
    const float* __restrict__ b1g, const float* __restrict__ b2g, float* __restrict__ out)
{
    extern __shared__ char smc[];
    uint32_t sb = smem_u32(smc);
    float* s_b1 = (float*)(smc + SM_B1);
    float* s_b2 = (float*)(smc + SM_B2);
    int tid = threadIdx.x, w = tid >> 5, lane = tid & 31;
    int pw = (w & 3) * 32, ow = (w >> 2) * 64;

    if (tid < 256) { s_b1[tid] = b1g[tid]; s_b2[tid] = b2g[tid]; }

    int g0 = blockIdx.x;

    // ---- one-time prologue: W1 + W2 + first A ----
    {
        const uint4* w14 = (const uint4*)g_W1f;
        const uint4* w24 = (const uint4*)g_W2f;
#pragma unroll
        for (int q = 0; q < 8; q++) {
            int idx = tid + q * 512;
            uint32_t off = swz(idx >> 4, (idx & 15) << 4);
            CP16(sb + SM_W1 + off, (const void*)(w14 + idx));
            CP16(sb + SM_W2 + off, (const void*)(w24 + idx));
        }
        if (g0 < NTILE) {
            const uint4* a4 = (const uint4*)(g_Af + (size_t)g0 * (128 * ND));
#pragma unroll
            for (int q = 0; q < 4; q++) {
                int idx = tid + q * 512;
                CP16(sb + SM_A + swz(idx >> 4, (idx & 15) << 4), (const void*)(a4 + idx));
            }
        }
        CP_COMMIT();
    }

    // operand lane patterns
    int arow = lane & 15;
    uint32_t acb = (uint32_t)(lane >> 4) << 4;
    int brow = ((lane >> 3) & 1) * 8 + (lane & 7);
    uint32_t bcb = (uint32_t)((lane >> 4) & 1) << 4;
    uint32_t uW1 = sb + SM_W1, uW2 = sb + SM_W2, uA = sb + SM_A;
    int lr = lane >> 2, lc = (lane & 3) << 1;
    int cW = ow >> 7;
    char* zB = smc + SM_Z + cW * 32768;
    int o2w = (w & 7) * 32, pw2 = (w >> 3) * 64;
    int ar2 = o2w + arow, br2 = pw2 + brow;
    int t4 = lane & 3;

    float acc[2][8][4];

    // ---- persistent tile loop ----
    for (int g = g0; g < NTILE; g += GRID_MAIN) {
        int b = g / NJ, j = g - b * NJ;

        CP_WAIT(0);          // A(t) landed
        __syncthreads();     // A visible; all warps past G2(t-1)

        // ---- GEMM1: D1[p=128][o=256] = A[p][d] * W1[o][d] ----
#pragma unroll
        for (int mt = 0; mt < 2; mt++)
#pragma unroll
            for (int nt = 0; nt < 8; nt++)
#pragma unroll
                for (int q = 0; q < 4; q++) acc[mt][nt][q] = 0.f;
        gemm_pipe<false>(uA, uW1, pw + arow, ow + brow, acb, bcb, acc);
        __syncthreads();     // all G1 A-reads done

        // ---- prefetch next tile's A (overlaps epi1 + GEMM2 + stores) ----
        {
            int gn = g + GRID_MAIN;
            if (gn < NTILE) {
                const uint4* a4 = (const uint4*)(g_Af + (size_t)gn * (128 * ND));
#pragma unroll
                for (int q = 0; q < 4; q++) {
                    int idx = tid + q * 512;
                    CP16(sb + SM_A + swz(idx >> 4, (idx & 15) << 4), (const void*)(a4 + idx));
                }
            }
            CP_COMMIT();
        }

        // ---- epilogue1: Z = relu(D1 + nf*b1) -> fp16 at PERMUTED rows ----
        float nf = (j == 0 || j == 256) ? 1.f : 2.f;
#pragma unroll
        for (int mt = 0; mt < 2; mt++) {
#pragma unroll
            for (int nt = 0; nt < 8; nt++) {
                int o = ow + nt * 8 + lc;
                int e = o & 127;
                float b0v = nf * s_b1[o], b1v = nf * s_b1[o + 1];
#pragma unroll
                for (int hf = 0; hf < 2; hf++) {
                    int p = pw + mt * 16 + lr + hf * 8;
                    int pl = p & 63;
                    int nl = ((pl >> 4) << 4) + (((pl >> 1) & 1) << 3)
                           + (((pl >> 2) & 3) << 1) + (pl & 1);
                    uint32_t row = (uint32_t)((p & 64) + nl);
                    __half2 hv;
                    hv.x = __float2half_rn(fmaxf(acc[mt][nt][hf * 2]     + b0v, 0.f));
                    hv.y = __float2half_rn(fmaxf(acc[mt][nt][hf * 2 + 1] + b1v, 0.f));
                    *(uint32_t*)(zB + swzZ(row, (uint32_t)e << 1)) = *(uint32_t*)&hv;
                }
            }
        }
        __syncthreads();     // Z visible to all

        // ---- GEMM2 (transposed): D2^T[o2=256][p=128] = W2[o2][e] * Z_c[p][e] ----
        int l0 = j * 128 - 64;
        bool valid = (j > 0 || pw2 == 64) && (j < 256 || pw2 == 0);
#pragma unroll 1
        for (int c = 0; c < 2; c++) {
            uint32_t uZ = sb + SM_Z + c * 32768;
#pragma unroll
            for (int mt = 0; mt < 2; mt++)
#pragma unroll
                for (int nt = 0; nt < 8; nt++)
#pragma unroll
                    for (int q = 0; q < 4; q++) acc[mt][nt][q] = 0.f;
            gemm_pipe<true>(uW2, uZ, ar2, br2, acb, bcb, acc);

            // ---- out epilogue: 4x float4 contiguous per row ----
            if (valid) {
                float* ob = out + (size_t)(b * 2 + c) * NO * TOUT;
#pragma unroll
                for (int mt = 0; mt < 2; mt++) {
#pragma unroll
                    for (int hf = 0; hf < 2; hf++) {
                        int o2 = o2w + mt * 16 + lr + hf * 8;
                        float bo = s_b2[o2];
                        float* orow = ob + (size_t)o2 * TOUT + l0 + pw2 + t4 * 4;
#pragma unroll
                        for (int q = 0; q < 4; q++) {
                            float4 v;
                            v.x = acc[mt][2 * q][hf * 2]         + bo;
                            v.y = acc[mt][2 * q][hf * 2 + 1]     + bo;
                            v.z = acc[mt][2 * q + 1][hf * 2]     + bo;
                            v.w = acc[mt][2 * q + 1][hf * 2 + 1] + bo;
                            *(float4*)(orow + 16 * q) = v;
                        }
                    }
                }
            }
        }
    }
}

// ---------------------------------------------------------------------------
extern "C" void kernel_launch(void* const* d_in, const int* in_sizes, int n_in,
                              void* d_out, int out_size) {
    const float* x  = (const float*)d_in[0];
    const float* pw = (const float*)d_in[1];
    const float* w1 = (const float*)d_in[2];
    const float* b1 = (const float*)d_in[3];
    const float* w2 = (const float*)d_in[4];
    const float* b2 = (const float*)d_in[5];
    float* out = (float*)d_out;

    cudaFuncSetAttribute(main_kernel, cudaFuncAttributeMaxDynamicSharedMemorySize, SM_TOT);

    prep_all<<<dim3(9, 2, NB * 128 + 1), dim3(32, 8)>>>(x, pw, w1, w2);
    main_kernel<<<GRID_MAIN, 512, SM_TOT>>>(b1, b2, out);
}

// round 17
// speedup vs baseline: 1.4076x; 1.0110x over previous
#include <cuda_runtime.h>
#include <cuda_fp16.h>
#include <cstdint>

#define NB 4
#define ND 128
#define NK 256
#define NS 256
#define NJ 257
#define NO 256
#define TOUT 32768
#define NTILE (NB * NJ)      // 1028
#define GRID_MAIN 148

// ---------------- scratch ----------------
__device__ __half g_Af[(size_t)NB*NJ*128*ND];   // presummed OLA frames, fp16 [b][j][p][d]
__device__ __half g_W1f[NO*ND];                 // [o][d]
__device__ __half g_W2f[NO*ND];                 // [o2][e]

// smem map (bytes)
#define SM_B1 0
#define SM_B2 1024
#define SM_W1 2048
#define SM_W2 (SM_W1 + 65536)
#define SM_A  (SM_W2 + 65536)
#define SM_Z  (SM_A + 32768)
#define SM_TOT (SM_Z + 65536)          // 231424

__device__ __forceinline__ uint32_t smem_u32(const void* p) {
    uint32_t a;
    asm("{ .reg .u64 t; cvta.to.shared.u64 t, %1; cvt.u32.u64 %0, t; }" : "=r"(a) : "l"(p));
    return a;
}
__device__ __forceinline__ uint32_t swz(uint32_t row, uint32_t byteCol) {
    return row * 256u + ((((byteCol >> 4) ^ (row & 7)) << 4) | (byteCol & 15));
}
__device__ __forceinline__ uint32_t swzZ(uint32_t row, uint32_t byteCol) {
    uint32_t f = (row ^ (row >> 3)) & 7u;
    return row * 256u + ((((byteCol >> 4) ^ f) << 4) | (byteCol & 15));
}
#define LDSM4(r0,r1,r2,r3,addr) \
    asm volatile("ldmatrix.sync.aligned.m8n8.x4.shared.b16 {%0,%1,%2,%3}, [%4];" \
        : "=r"(r0),"=r"(r1),"=r"(r2),"=r"(r3) : "r"(addr))
#define CP16(dst, src) \
    asm volatile("cp.async.cg.shared.global [%0], [%1], 16;" :: "r"(dst), "l"(src) : "memory")
#define CP_COMMIT() asm volatile("cp.async.commit_group;" ::: "memory")
#define CP_WAIT(n)  asm volatile("cp.async.wait_group %0;" :: "n"(n) : "memory")
#define BAR_ARRIVE(id, cnt) asm volatile("bar.arrive %0, %1;" :: "r"(id), "r"(cnt) : "memory")
#define BAR_SYNC(id, cnt)   asm volatile("bar.sync %0, %1;"   :: "r"(id), "r"(cnt) : "memory")

__device__ __forceinline__ void mma16816(float d[4], const uint32_t a[4], uint32_t b0, uint32_t b1) {
    asm volatile("mma.sync.aligned.m16n8k16.row.col.f32.f16.f16.f32 "
        "{%0,%1,%2,%3}, {%4,%5,%6,%7}, {%8,%9}, {%0,%1,%2,%3};"
        : "+f"(d[0]), "+f"(d[1]), "+f"(d[2]), "+f"(d[3])
        : "r"(a[0]), "r"(a[1]), "r"(a[2]), "r"(a[3]), "r"(b0), "r"(b1));
}

// 32x64 warp-tile GEMM over K=128 with explicit fragment double-buffering (proven R13).
template<bool BZ>
__device__ __forceinline__ void gemm_pipe(uint32_t uAop, uint32_t uBop,
                                          int ar, int br, uint32_t acb, uint32_t bcb,
                                          float acc[2][8][4])
{
    uint32_t af[2][2][4], bf[2][4][4];
#pragma unroll
    for (int mt = 0; mt < 2; mt++)
        LDSM4(af[0][mt][0], af[0][mt][1], af[0][mt][2], af[0][mt][3],
              uAop + swz(ar + mt * 16, acb));
#pragma unroll
    for (int ng = 0; ng < 4; ng++) {
        uint32_t off = BZ ? swzZ(br + ng * 16, bcb) : swz(br + ng * 16, bcb);
        LDSM4(bf[0][ng][0], bf[0][ng][1], bf[0][ng][2], bf[0][ng][3], uBop + off);
    }
#pragma unroll
    for (int ks = 0; ks < 8; ks++) {
        int cur = ks & 1, nxt = cur ^ 1;
        if (ks < 7) {
            uint32_t kb = (uint32_t)(ks + 1) * 32;
#pragma unroll
            for (int mt = 0; mt < 2; mt++)
                LDSM4(af[nxt][mt][0], af[nxt][mt][1], af[nxt][mt][2], af[nxt][mt][3],
                      uAop + swz(ar + mt * 16, kb + acb));
#pragma unroll
            for (int ng = 0; ng < 4; ng++) {
                uint32_t off = BZ ? swzZ(br + ng * 16, kb + bcb) : swz(br + ng * 16, kb + bcb);
                LDSM4(bf[nxt][ng][0], bf[nxt][ng][1], bf[nxt][ng][2], bf[nxt][ng][3], uBop + off);
            }
        }
#pragma unroll
        for (int mt = 0; mt < 2; mt++)
#pragma unroll
            for (int ng = 0; ng < 4; ng++) {
                mma16816(acc[mt][2 * ng],     af[cur][mt], bf[cur][ng][0], bf[cur][ng][2]);
                mma16816(acc[mt][2 * ng + 1], af[cur][mt], bf[cur][ng][1], bf[cur][ng][3]);
            }
    }
}

// ---------------- prep: W fp16 convert + OLA-presummed A (proven; at DRAM roofline) ----------------
__global__ void prep_all(const float* __restrict__ x, const float* __restrict__ pw_ptr,
                         const float* __restrict__ w1, const float* __restrict__ w2)
{
    int tx = threadIdx.x, ty = threadIdx.y;
    int tid = ty * 32 + tx;
    if (blockIdx.z == NB * 128) {
        int flat = ((int)blockIdx.x * 2 + (int)blockIdx.y) * 256 + tid;
        for (; flat < 2 * NO * ND; flat += 18 * 256) {
            if (flat < NO * ND) g_W1f[flat] = __float2half_rn(w1[flat]);
            else                g_W2f[flat - NO * ND] = __float2half_rn(w2[flat - NO * ND]);
        }
        return;
    }
    __shared__ float t[64][33];
    int b = blockIdx.z >> 7, p = blockIdx.z & 127;
    int j0 = blockIdx.x * 32, d0 = blockIdx.y * 64;
    float pw = *pw_ptr;
#pragma unroll
    for (int i = 0; i < 8; i++) {
        int d = d0 + ty + i * 8;
        int jj = j0 + tx;
        float acc = 0.f;
        if (jj < 256) {
            float v = x[(((size_t)b * ND + d) * NK + p) * NS + jj];
            acc += (v >= 0.f) ? v : pw * v;
        }
        if (jj >= 1 && jj <= 256) {
            float v = x[(((size_t)b * ND + d) * NK + p + 128) * NS + jj - 1];
            acc += (v >= 0.f) ? v : pw * v;
        }
        t[ty + i * 8][tx] = acc;
    }
    __syncthreads();
#pragma unroll
    for (int i = 0; i < 4; i++) {
        int jl = ty + i * 8;
        int jj = j0 + jl;
        if (jj <= 256) {
            __half2 hv;
            hv.x = __float2half_rn(t[2 * tx][jl]);
            hv.y = __float2half_rn(t[2 * tx + 1][jl]);
            *(__half2*)&g_Af[(((size_t)b * NJ + jj) * 128 + p) * ND + d0 + 2 * tx] = hv;
        }
    }
}

// ---------------- persistent fused main kernel ----------------
__global__ __launch_bounds__(512, 1) void main_kernel(
    const float* __restrict__ b1g, const float* __restrict__ b2g, float* __restrict__ out)
{
    extern __shared__ char smc[];
    uint32_t sb = smem_u32(smc);
    float* s_b1 = (float*)(smc + SM_B1);
    float* s_b2 = (float*)(smc + SM_B2);
    int tid = threadIdx.x, w = tid >> 5, lane = tid & 31;
    int pw = (w & 3) * 32, ow = (w >> 2) * 64;

    if (tid < 256) { s_b1[tid] = b1g[tid]; s_b2[tid] = b2g[tid]; }

    int g0 = blockIdx.x;

    // ---- one-time prologue: W1 + W2 + first A ----
    {
        const uint4* w14 = (const uint4*)g_W1f;
        const uint4* w24 = (const uint4*)g_W2f;
#pragma unroll
        for (int q = 0; q < 8; q++) {
            int idx = tid + q * 512;
            uint32_t off = swz(idx >> 4, (idx & 15) << 4);
            CP16(sb + SM_W1 + off, (const void*)(w14 + idx));
            CP16(sb + SM_W2 + off, (const void*)(w24 + idx));
        }
        if (g0 < NTILE) {
            const uint4* a4 = (const uint4*)(g_Af + (size_t)g0 * (128 * ND));
#pragma unroll
            for (int q = 0; q < 4; q++) {
                int idx = tid + q * 512;
                CP16(sb + SM_A + swz(idx >> 4, (idx & 15) << 4), (const void*)(a4 + idx));
            }
        }
        CP_COMMIT();
    }

    // operand lane patterns
    int arow = lane & 15;
    uint32_t acb = (uint32_t)(lane >> 4) << 4;
    int brow = ((lane >> 3) & 1) * 8 + (lane & 7);
    uint32_t bcb = (uint32_t)((lane >> 4) & 1) << 4;
    uint32_t uW1 = sb + SM_W1, uW2 = sb + SM_W2, uA = sb + SM_A;
    int lr = lane >> 2, lc = (lane & 3) << 1;
    int cW = ow >> 7;                        // which Z channel this warp produces
    char* zB = smc + SM_Z + cW * 32768;
    int o2w = (w & 7) * 32, pw2 = (w >> 3) * 64;
    int ar2 = o2w + arow, br2 = pw2 + brow;
    int t4 = lane & 3;

    // epi1 hoisted addressing: 4 (mt,hf) rows per thread (permuted row + swizzle factor)
    uint32_t zrb[2][2];   // row*256 + 2*lc
    uint32_t zf[2][2];    // swizzle XOR factor
#pragma unroll
    for (int mt = 0; mt < 2; mt++)
#pragma unroll
        for (int hf = 0; hf < 2; hf++) {
            int p = pw + mt * 16 + lr + hf * 8;
            int pl = p & 63;
            int nl = ((pl >> 4) << 4) + (((pl >> 1) & 1) << 3)
                   + (((pl >> 2) & 3) << 1) + (pl & 1);
            uint32_t row = (uint32_t)((p & 64) + nl);
            zf[mt][hf] = (row ^ (row >> 3)) & 7u;
            zrb[mt][hf] = row * 256u + (uint32_t)(2 * lc);
        }
    // channel-local column base: e = (o & 127) >> 3 = ((ow & 64) >> 3) + nt   [BUGFIX vs R16]
    uint32_t ow8m = (uint32_t)((ow & 64) >> 3);

    float acc[2][8][4];

    // ---- persistent tile loop ----
    for (int g = g0; g < NTILE; g += GRID_MAIN) {
        int b = g / NJ, j = g - b * NJ;

        CP_WAIT(0);          // A(t) landed
        __syncthreads();     // A visible; all warps past G2(t-1)

        // ---- GEMM1: D1[p=128][o=256] = A[p][d] * W1[o][d] ----
#pragma unroll
        for (int mt = 0; mt < 2; mt++)
#pragma unroll
            for (int nt = 0; nt < 8; nt++)
#pragma unroll
                for (int q = 0; q < 4; q++) acc[mt][nt][q] = 0.f;
        gemm_pipe<false>(uA, uW1, pw + arow, ow + brow, acb, bcb, acc);
        __syncthreads();     // all G1 A-reads done

        // ---- prefetch next tile's A (overlaps epi1 + GEMM2 + stores) ----
        {
            int gn = g + GRID_MAIN;
            if (gn < NTILE) {
                const uint4* a4 = (const uint4*)(g_Af + (size_t)gn * (128 * ND));
#pragma unroll
                for (int q = 0; q < 4; q++) {
                    int idx = tid + q * 512;
                    CP16(sb + SM_A + swz(idx >> 4, (idx & 15) << 4), (const void*)(a4 + idx));
                }
            }
            CP_COMMIT();
        }

        // ---- epilogue1: Z = relu(D1 + nf*b1) -> fp16 at PERMUTED rows (hoisted addr) ----
        float nf = (j == 0 || j == 256) ? 1.f : 2.f;
#pragma unroll
        for (int mt = 0; mt < 2; mt++) {
#pragma unroll
            for (int nt = 0; nt < 8; nt++) {
                int o = ow + nt * 8 + lc;
                float b0v = nf * s_b1[o], b1v = nf * s_b1[o + 1];
                uint32_t colx = ow8m + (uint32_t)nt;      // channel-local column (fixed)
#pragma unroll
                for (int hf = 0; hf < 2; hf++) {
                    __half2 hv;
                    hv.x = __float2half_rn(fmaxf(acc[mt][nt][hf * 2]     + b0v, 0.f));
                    hv.y = __float2half_rn(fmaxf(acc[mt][nt][hf * 2 + 1] + b1v, 0.f));
                    uint32_t off = zrb[mt][hf] + ((colx ^ zf[mt][hf]) << 4);
                    *(uint32_t*)(zB + off) = *(uint32_t*)&hv;
                }
            }
        }
        // signal own Z half complete (768 = 256 producer arrivals + 512 sync arrivals)
        if (cW == 0) BAR_ARRIVE(1, 768);
        else         BAR_ARRIVE(2, 768);

        // ---- GEMM2 (transposed): per channel, gated by its producer barrier ----
        int l0 = j * 128 - 64;
        bool valid = (j > 0 || pw2 == 64) && (j < 256 || pw2 == 0);
#pragma unroll 1
        for (int c = 0; c < 2; c++) {
            if (c == 0) BAR_SYNC(1, 768);    // Zc0 ready
            else        BAR_SYNC(2, 768);    // Zc1 ready
            uint32_t uZ = sb + SM_Z + c * 32768;
#pragma unroll
            for (int mt = 0; mt < 2; mt++)
#pragma unroll
                for (int nt = 0; nt < 8; nt++)
#pragma unroll
                    for (int q = 0; q < 4; q++) acc[mt][nt][q] = 0.f;
            gemm_pipe<true>(uW2, uZ, ar2, br2, acb, bcb, acc);

            // ---- out epilogue: 4x float4 contiguous per row, streaming stores ----
            if (valid) {
                float* ob = out + (size_t)(b * 2 + c) * NO * TOUT;
#pragma unroll
                for (int mt = 0; mt < 2; mt++) {
#pragma unroll
                    for (int hf = 0; hf < 2; hf++) {
                        int o2 = o2w + mt * 16 + lr + hf * 8;
                        float bo = s_b2[o2];
                        float* orow = ob + (size_t)o2 * TOUT + l0 + pw2 + t4 * 4;
#pragma unroll
                        for (int q = 0; q < 4; q++) {
                            float4 v;
                            v.x = acc[mt][2 * q][hf * 2]         + bo;
                            v.y = acc[mt][2 * q][hf * 2 + 1]     + bo;
                            v.z = acc[mt][2 * q + 1][hf * 2]     + bo;
                            v.w = acc[mt][2 * q + 1][hf * 2 + 1] + bo;
                            __stcs((float4*)(orow + 16 * q), v);
                        }
                    }
                }
            }
        }
    }
}

// ---------------------------------------------------------------------------
extern "C" void kernel_launch(void* const* d_in, const int* in_sizes, int n_in,
                              void* d_out, int out_size) {
    const float* x  = (const float*)d_in[0];
    const float* pw = (const float*)d_in[1];
    const float* w1 = (const float*)d_in[2];
    const float* b1 = (const float*)d_in[3];
    const float* w2 = (const float*)d_in[4];
    const float* b2 = (const float*)d_in[5];
    float* out = (float*)d_out;

    cudaFuncSetAttribute(main_kernel, cudaFuncAttributeMaxDynamicSharedMemorySize, SM_TOT);

    prep_all<<<dim3(9, 2, NB * 128 + 1), dim3(32, 8)>>>(x, pw, w1, w2);
    main_kernel<<<GRID_MAIN, 512, SM_TOT>>>(b1, b2, out);
}